// round 6
// baseline (speedup 1.0000x reference)
#include <cuda_runtime.h>
#include <cuda_bf16.h>
#include <cstdint>
#include <cstddef>

#define LOG2E 1.4426950408889634f
#define LN2   0.6931471805599453f

// ---- static scratch ----
__device__ float g_cost[64 * 512 * 256];        // diag layout [b][i+j][j], log2e-scaled
__device__ float g_xn[64 * 256];                // log2e * |x_i|^2
__device__ float g_yn[64 * 256];
__device__ unsigned short g_xb[64 * 256 * 128]; // bf16 bits of x
__device__ unsigned short g_yb[64 * 256 * 128]; // bf16 bits of y

__device__ __forceinline__ float ex2f(float x) {
    float y; asm("ex2.approx.f32 %0, %1;" : "=f"(y) : "f"(x)); return y;
}
__device__ __forceinline__ float lg2f(float x) {
    float y; asm("lg2.approx.f32 %0, %1;" : "=f"(y) : "f"(x)); return y;
}
__device__ __forceinline__ uint32_t sptr(const void* p) {
    return (uint32_t)__cvta_generic_to_shared(p);
}

// ================= K0: norms + bf16 convert (warp per row) =================
__global__ void __launch_bounds__(256) prep_kernel(const float* __restrict__ x,
                                                   const float* __restrict__ y,
                                                   float* __restrict__ out) {
    int gw = blockIdx.x * 8 + (threadIdx.x >> 5);
    int lane = threadIdx.x & 31;
    bool isx = gw < 16384;
    int rowg = isx ? gw : gw - 16384;  // b*256 + r
    const float* src = (isx ? x : y) + (size_t)rowg * 128 + lane * 4;
    float4 f = *(const float4*)src;
    float s = f.x * f.x;
    s = fmaf(f.y, f.y, s); s = fmaf(f.z, f.z, s); s = fmaf(f.w, f.w, s);
#pragma unroll
    for (int off = 16; off >= 1; off >>= 1) s += __shfl_xor_sync(0xffffffffu, s, off);
    if (lane == 0) (isx ? g_xn : g_yn)[rowg] = s * LOG2E;
    ushort4 s4;
    s4.x = __bfloat16_as_ushort(__float2bfloat16(f.x));
    s4.y = __bfloat16_as_ushort(__float2bfloat16(f.y));
    s4.z = __bfloat16_as_ushort(__float2bfloat16(f.z));
    s4.w = __bfloat16_as_ushort(__float2bfloat16(f.w));
    *(ushort4*)((isx ? g_xb : g_yb) + (size_t)rowg * 128 + lane * 4) = s4;
    if (blockIdx.x == 0 && threadIdx.x == 0) out[0] = 0.f;
}

// ================= K1: bf16 mma cost GEMM, diag-coalesced epilogue =================
// 256 blocks = 64 batches x (2x2 tiles of 128x128). 8 warps, warp tile 32(m) x 64(n).
__global__ void __launch_bounds__(256) cost_gemm_kernel() {
    __shared__ __align__(16) char smraw[33280];
    unsigned short* Xs = (unsigned short*)smraw;       // [128][64] bf16, swizzled
    unsigned short* Ys = Xs + 128 * 64;
    float* Cs = (float*)smraw;                          // [64][130]

    int bx = blockIdx.x;
    int b = bx >> 2, tm = (bx >> 1) & 1, tn = bx & 1;
    int t = threadIdx.x, lane = t & 31, w = t >> 5;
    int wr = w >> 1, wc = w & 1;

    const unsigned short* Xg = g_xb + ((size_t)(b * 256 + tm * 128)) * 128;
    const unsigned short* Yg = g_yb + ((size_t)(b * 256 + tn * 128)) * 128;

    float acc[2][8][4];
#pragma unroll
    for (int am = 0; am < 2; am++)
#pragma unroll
        for (int bn = 0; bn < 8; bn++)
#pragma unroll
            for (int k = 0; k < 4; k++) acc[am][bn][k] = 0.f;

    int arow0 = 32 * wr + (lane & 15);
    int ahalf = lane >> 4;
    int brow0 = 64 * wc + (lane & 7) + ((lane >> 4) << 3);
    int bhalf = (lane >> 3) & 1;

    for (int kc = 0; kc < 128; kc += 64) {
        __syncthreads();
#pragma unroll
        for (int p = 0; p < 4; p++) {
            int u = t + 256 * p;
            int row = u >> 3, c16 = u & 7;
            uint4 vx = *(const uint4*)(Xg + (size_t)row * 128 + kc + c16 * 8);
            uint4 vy = *(const uint4*)(Yg + (size_t)row * 128 + kc + c16 * 8);
            int soff = row * 128 + ((c16 ^ (row & 7)) << 4);
            *(uint4*)((char*)Xs + soff) = vx;
            *(uint4*)((char*)Ys + soff) = vy;
        }
        __syncthreads();
#pragma unroll
        for (int ks = 0; ks < 4; ks++) {
            uint32_t a[2][4], bf[8][2];
#pragma unroll
            for (int am = 0; am < 2; am++) {
                int row = arow0 + 16 * am;
                int kb16 = ks * 2 + ahalf;
                uint32_t ad = sptr((char*)Xs + row * 128 + ((kb16 ^ (row & 7)) << 4));
                asm volatile("ldmatrix.sync.aligned.m8n8.x4.shared.b16 {%0,%1,%2,%3},[%4];"
                    : "=r"(a[am][0]), "=r"(a[am][1]), "=r"(a[am][2]), "=r"(a[am][3]) : "r"(ad));
            }
#pragma unroll
            for (int bp = 0; bp < 4; bp++) {
                int row = brow0 + 16 * bp;
                int kb16 = ks * 2 + bhalf;
                uint32_t ad = sptr((char*)Ys + row * 128 + ((kb16 ^ (row & 7)) << 4));
                asm volatile("ldmatrix.sync.aligned.m8n8.x4.shared.b16 {%0,%1,%2,%3},[%4];"
                    : "=r"(bf[2 * bp][0]), "=r"(bf[2 * bp][1]),
                      "=r"(bf[2 * bp + 1][0]), "=r"(bf[2 * bp + 1][1]) : "r"(ad));
            }
#pragma unroll
            for (int am = 0; am < 2; am++)
#pragma unroll
                for (int bn = 0; bn < 8; bn++)
                    asm volatile("mma.sync.aligned.m16n8k16.row.col.f32.bf16.bf16.f32 "
                        "{%0,%1,%2,%3},{%4,%5,%6,%7},{%8,%9},{%0,%1,%2,%3};"
                        : "+f"(acc[am][bn][0]), "+f"(acc[am][bn][1]),
                          "+f"(acc[am][bn][2]), "+f"(acc[am][bn][3])
                        : "r"(a[am][0]), "r"(a[am][1]), "r"(a[am][2]), "r"(a[am][3]),
                          "r"(bf[bn][0]), "r"(bf[bn][1]));
        }
    }

    // epilogue: stage to smem in 2 row-halves, then coalesced diag-major stores
    __syncthreads();
    float* cb = g_cost + (size_t)b * 512 * 256;
    const float* xn = g_xn + b * 256;
    const float* yn = g_yn + b * 256;

#pragma unroll
    for (int h = 0; h < 2; h++) {
        if ((wr >> 1) == h) {
            int rbase = 32 * (wr & 1);
#pragma unroll
            for (int am = 0; am < 2; am++)
#pragma unroll
                for (int bn = 0; bn < 8; bn++) {
                    int rr = rbase + 16 * am + (lane >> 2);
                    int cc = 64 * wc + 8 * bn + 2 * (lane & 3);
                    *(float2*)&Cs[rr * 130 + cc] = make_float2(acc[am][bn][0], acc[am][bn][1]);
                    *(float2*)&Cs[(rr + 8) * 130 + cc] = make_float2(acc[am][bn][2], acc[am][bn][3]);
                }
        }
        __syncthreads();
        int tt = t & 127;
        for (int s2 = 0; s2 < 192; s2 += 2) {
            int s = s2 + (t >> 7);                 // local diag within half: 0..191
            int lj_lo = max(0, s - 63), lj_hi = min(127, s);
            int lj = lj_lo + tt;
            if (s < 191 && lj <= lj_hi) {
                int li = s - lj;
                int i = tm * 128 + 64 * h + li;
                int j = tn * 128 + lj;
                float v = xn[i] + yn[j] - (2.0f * LOG2E) * Cs[li * 130 + lj];
                cb[(size_t)(i + j) * 256 + j] = v;
            }
        }
        __syncthreads();
    }
}

// ================= K2: warp-per-2-batches soft-DTW (no sync primitives) =================
// 32 blocks, 1 warp each, 2 independent batches interleaved per warp for latency hiding.
// Lane l owns columns j = 8l+1 .. 8l+8 per batch; 2 shfl per batch per step.
struct DpState {
    float r1[8], r2[8];
    float4 p0a, p0b, p1a, p1b;
};

__device__ __forceinline__ void dp_step(DpState& S, const float* __restrict__ cost,
                                        int d, int jbase, int lane) {
    const float INF = __int_as_float(0x7f800000);
    float cc[8];
    cc[0] = S.p0a.x; cc[1] = S.p0a.y; cc[2] = S.p0a.z; cc[3] = S.p0a.w;
    cc[4] = S.p0b.x; cc[5] = S.p0b.y; cc[6] = S.p0b.z; cc[7] = S.p0b.w;
    S.p0a = S.p1a; S.p0b = S.p1b;
    if (d <= 510) {
        S.p1a = *(const float4*)(cost + (size_t)d * 256);
        S.p1b = *(const float4*)(cost + (size_t)d * 256 + 4);
    }
    float lb1 = __shfl_up_sync(0xffffffffu, S.r1[7], 1);
    float lb2 = __shfl_up_sync(0xffffffffu, S.r2[7], 1);
    if (lane == 0) { lb1 = INF; lb2 = (d == 2) ? 0.0f : INF; }
#pragma unroll
    for (int c = 7; c >= 0; --c) {
        float up   = S.r1[c];
        float left = c ? S.r1[c - 1] : lb1;
        float dg   = c ? S.r2[c - 1] : lb2;
        float mn = fminf(up, left), mx = fmaxf(up, left);
        float lo  = fminf(mn, dg);
        float mid = fmaxf(mn, fminf(mx, dg));
        float hi  = fmaxf(mx, dg);
        float rn = cc[c] + lo - lg2f(1.0f + ex2f(lo - mid) + ex2f(lo - hi));
        unsigned im1 = (unsigned)(d - (jbase + c)) - 1u;  // i-1
        S.r2[c] = S.r1[c];
        if (im1 < 256u) S.r1[c] = rn;
    }
}

__global__ void __launch_bounds__(32) dp_kernel(float* __restrict__ out) {
    int lane = threadIdx.x;
    int b0 = blockIdx.x * 2;
    const float INF = __int_as_float(0x7f800000);
    const float* costA = g_cost + (size_t)b0 * 512 * 256 + lane * 8;
    const float* costB = g_cost + (size_t)(b0 + 1) * 512 * 256 + lane * 8;

    DpState A, B;
#pragma unroll
    for (int c = 0; c < 8; c++) { A.r1[c] = INF; A.r2[c] = INF; B.r1[c] = INF; B.r2[c] = INF; }

    A.p0a = *(const float4*)(costA + 0 * 256);
    A.p0b = *(const float4*)(costA + 0 * 256 + 4);
    A.p1a = *(const float4*)(costA + 1 * 256);
    A.p1b = *(const float4*)(costA + 1 * 256 + 4);
    B.p0a = *(const float4*)(costB + 0 * 256);
    B.p0b = *(const float4*)(costB + 0 * 256 + 4);
    B.p1a = *(const float4*)(costB + 1 * 256);
    B.p1b = *(const float4*)(costB + 1 * 256 + 4);

    int jbase = 8 * lane + 1;

    for (int d = 2; d <= 512; ++d) {
        dp_step(A, costA, d, jbase, lane);
        dp_step(B, costB, d, jbase, lane);
    }

    if (lane == 31) {
        atomicAdd(out, A.r1[7] * (LN2 / 64.0f));
        atomicAdd(out, B.r1[7] * (LN2 / 64.0f));
    }
}

extern "C" void kernel_launch(void* const* d_in, const int* in_sizes, int n_in,
                              void* d_out, int out_size) {
    const float* x = (const float*)d_in[0];
    const float* y = (const float*)d_in[1];
    float* out = (float*)d_out;
    prep_kernel<<<4096, 256>>>(x, y, out);
    cost_gemm_kernel<<<256, 256>>>();
    dp_kernel<<<32, 32>>>(out);
}

// round 9
// speedup vs baseline: 2.3979x; 2.3979x over previous
#include <cuda_runtime.h>
#include <cuda_bf16.h>
#include <cstdint>
#include <cstddef>

#define LOG2E 1.4426950408889634f
#define LN2   0.6931471805599453f

// ---- static scratch ----
__device__ float g_cost[64 * 512 * 256];        // diag layout [b][i+j][j], log2e-scaled
__device__ float g_xn[64 * 256];                // log2e * |x_i|^2
__device__ float g_yn[64 * 256];
__device__ unsigned short g_xb[64 * 256 * 128]; // bf16 bits of x
__device__ unsigned short g_yb[64 * 256 * 128]; // bf16 bits of y

__device__ __forceinline__ float ex2f(float x) {
    float y; asm("ex2.approx.f32 %0, %1;" : "=f"(y) : "f"(x)); return y;
}
__device__ __forceinline__ float lg2f(float x) {
    float y; asm("lg2.approx.f32 %0, %1;" : "=f"(y) : "f"(x)); return y;
}
__device__ __forceinline__ uint32_t sptr(const void* p) {
    return (uint32_t)__cvta_generic_to_shared(p);
}

// ================= K0: norms + bf16 convert (warp per row) =================
__global__ void __launch_bounds__(256) prep_kernel(const float* __restrict__ x,
                                                   const float* __restrict__ y,
                                                   float* __restrict__ out) {
    int gw = blockIdx.x * 8 + (threadIdx.x >> 5);
    int lane = threadIdx.x & 31;
    bool isx = gw < 16384;
    int rowg = isx ? gw : gw - 16384;  // b*256 + r
    const float* src = (isx ? x : y) + (size_t)rowg * 128 + lane * 4;
    float4 f = *(const float4*)src;
    float s = f.x * f.x;
    s = fmaf(f.y, f.y, s); s = fmaf(f.z, f.z, s); s = fmaf(f.w, f.w, s);
#pragma unroll
    for (int off = 16; off >= 1; off >>= 1) s += __shfl_xor_sync(0xffffffffu, s, off);
    if (lane == 0) (isx ? g_xn : g_yn)[rowg] = s * LOG2E;
    ushort4 s4;
    s4.x = __bfloat16_as_ushort(__float2bfloat16(f.x));
    s4.y = __bfloat16_as_ushort(__float2bfloat16(f.y));
    s4.z = __bfloat16_as_ushort(__float2bfloat16(f.z));
    s4.w = __bfloat16_as_ushort(__float2bfloat16(f.w));
    *(ushort4*)((isx ? g_xb : g_yb) + (size_t)rowg * 128 + lane * 4) = s4;
    if (blockIdx.x == 0 && threadIdx.x == 0) out[0] = 0.f;
}

// ================= K1: bf16 mma cost GEMM, diag-coalesced epilogue =================
// 256 blocks = 64 batches x (2x2 tiles of 128x128). 8 warps, warp tile 32(m) x 64(n).
__global__ void __launch_bounds__(256) cost_gemm_kernel() {
    __shared__ __align__(16) char smraw[33280];
    unsigned short* Xs = (unsigned short*)smraw;       // [128][64] bf16, swizzled
    unsigned short* Ys = Xs + 128 * 64;
    float* Cs = (float*)smraw;                          // [64][130]

    int bx = blockIdx.x;
    int b = bx >> 2, tm = (bx >> 1) & 1, tn = bx & 1;
    int t = threadIdx.x, lane = t & 31, w = t >> 5;
    int wr = w >> 1, wc = w & 1;

    const unsigned short* Xg = g_xb + ((size_t)(b * 256 + tm * 128)) * 128;
    const unsigned short* Yg = g_yb + ((size_t)(b * 256 + tn * 128)) * 128;

    float acc[2][8][4];
#pragma unroll
    for (int am = 0; am < 2; am++)
#pragma unroll
        for (int bn = 0; bn < 8; bn++)
#pragma unroll
            for (int k = 0; k < 4; k++) acc[am][bn][k] = 0.f;

    int arow0 = 32 * wr + (lane & 15);
    int ahalf = lane >> 4;
    int brow0 = 64 * wc + (lane & 7) + ((lane >> 4) << 3);
    int bhalf = (lane >> 3) & 1;

    for (int kc = 0; kc < 128; kc += 64) {
        __syncthreads();
#pragma unroll
        for (int p = 0; p < 4; p++) {
            int u = t + 256 * p;
            int row = u >> 3, c16 = u & 7;
            uint4 vx = *(const uint4*)(Xg + (size_t)row * 128 + kc + c16 * 8);
            uint4 vy = *(const uint4*)(Yg + (size_t)row * 128 + kc + c16 * 8);
            int soff = row * 128 + ((c16 ^ (row & 7)) << 4);
            *(uint4*)((char*)Xs + soff) = vx;
            *(uint4*)((char*)Ys + soff) = vy;
        }
        __syncthreads();
#pragma unroll
        for (int ks = 0; ks < 4; ks++) {
            uint32_t a[2][4], bf[8][2];
#pragma unroll
            for (int am = 0; am < 2; am++) {
                int row = arow0 + 16 * am;
                int kb16 = ks * 2 + ahalf;
                uint32_t ad = sptr((char*)Xs + row * 128 + ((kb16 ^ (row & 7)) << 4));
                asm volatile("ldmatrix.sync.aligned.m8n8.x4.shared.b16 {%0,%1,%2,%3},[%4];"
                    : "=r"(a[am][0]), "=r"(a[am][1]), "=r"(a[am][2]), "=r"(a[am][3]) : "r"(ad));
            }
#pragma unroll
            for (int bp = 0; bp < 4; bp++) {
                int row = brow0 + 16 * bp;
                int kb16 = ks * 2 + bhalf;
                uint32_t ad = sptr((char*)Ys + row * 128 + ((kb16 ^ (row & 7)) << 4));
                asm volatile("ldmatrix.sync.aligned.m8n8.x4.shared.b16 {%0,%1,%2,%3},[%4];"
                    : "=r"(bf[2 * bp][0]), "=r"(bf[2 * bp][1]),
                      "=r"(bf[2 * bp + 1][0]), "=r"(bf[2 * bp + 1][1]) : "r"(ad));
            }
#pragma unroll
            for (int am = 0; am < 2; am++)
#pragma unroll
                for (int bn = 0; bn < 8; bn++)
                    asm volatile("mma.sync.aligned.m16n8k16.row.col.f32.bf16.bf16.f32 "
                        "{%0,%1,%2,%3},{%4,%5,%6,%7},{%8,%9},{%0,%1,%2,%3};"
                        : "+f"(acc[am][bn][0]), "+f"(acc[am][bn][1]),
                          "+f"(acc[am][bn][2]), "+f"(acc[am][bn][3])
                        : "r"(a[am][0]), "r"(a[am][1]), "r"(a[am][2]), "r"(a[am][3]),
                          "r"(bf[bn][0]), "r"(bf[bn][1]));
        }
    }

    // epilogue: stage to smem in 2 row-halves, then coalesced diag-major stores
    __syncthreads();
    float* cb = g_cost + (size_t)b * 512 * 256;
    const float* xn = g_xn + b * 256;
    const float* yn = g_yn + b * 256;

#pragma unroll
    for (int h = 0; h < 2; h++) {
        if ((wr >> 1) == h) {
            int rbase = 32 * (wr & 1);
#pragma unroll
            for (int am = 0; am < 2; am++)
#pragma unroll
                for (int bn = 0; bn < 8; bn++) {
                    int rr = rbase + 16 * am + (lane >> 2);
                    int cc = 64 * wc + 8 * bn + 2 * (lane & 3);
                    *(float2*)&Cs[rr * 130 + cc] = make_float2(acc[am][bn][0], acc[am][bn][1]);
                    *(float2*)&Cs[(rr + 8) * 130 + cc] = make_float2(acc[am][bn][2], acc[am][bn][3]);
                }
        }
        __syncthreads();
        int tt = t & 127;
        for (int s2 = 0; s2 < 192; s2 += 2) {
            int s = s2 + (t >> 7);                 // local diag within half: 0..191
            int lj_lo = max(0, s - 63), lj_hi = min(127, s);
            int lj = lj_lo + tt;
            if (s < 191 && lj <= lj_hi) {
                int li = s - lj;
                int i = tm * 128 + 64 * h + li;
                int j = tn * 128 + lj;
                float v = xn[i] + yn[j] - (2.0f * LOG2E) * Cs[li * 130 + lj];
                cb[(size_t)(i + j) * 256 + j] = v;
            }
        }
        __syncthreads();
    }
}

// ================= K2: 8-warp wavefront soft-DTW (1 cell/thread, shfl + 1 barrier/step) ====
// One block per batch, 256 threads, thread t owns column j = t+1.
// Intra-warp neighbors via shfl_up; warp boundary (lane31 -> next warp's lane0) via
// parity-double-buffered smem written once per step. One __syncthreads per diagonal.
__global__ void __launch_bounds__(256) dp_kernel(float* __restrict__ out) {
    __shared__ float2 bnd[2][8];   // [parity][warp] = {r1, r2} of that warp's lane 31

    int t = threadIdx.x, lane = t & 31, w = t >> 5, b = blockIdx.x;
    const float INF = __int_as_float(0x7f800000);
    const float* cost = g_cost + (size_t)b * 512 * 256 + t;

    float r1 = INF, r2 = INF;          // own column's R at d-1, d-2
    float cp0 = cost[0];               // feeds d = 2
    float cp1 = cost[256];             // feeds d = 3
    if (t < 16) ((float2*)bnd)[t] = make_float2(INF, INF);
    __syncthreads();

    int j = t + 1;
    for (int d = 2; d <= 512; ++d) {
        float cc = cp0; cp0 = cp1;
        if (d <= 510) cp1 = cost[(size_t)d * 256];

        float lb1 = __shfl_up_sync(0xffffffffu, r1, 1);   // R[i][j-1]
        float lb2 = __shfl_up_sync(0xffffffffu, r2, 1);   // R[i-1][j-1]
        if (lane == 0) {
            if (w == 0) { lb1 = INF; lb2 = (d == 2) ? 0.0f : INF; }
            else { float2 v = bnd[(d - 1) & 1][w - 1]; lb1 = v.x; lb2 = v.y; }
        }

        float up = r1;                 // R[i-1][j]
        float mn = fminf(up, lb1), mx = fmaxf(up, lb1);
        float lo  = fminf(mn, lb2);
        float mid = fmaxf(mn, fminf(mx, lb2));
        float hi  = fmaxf(mx, lb2);
        float rn = cc + lo - lg2f(1.0f + ex2f(lo - mid) + ex2f(lo - hi));

        unsigned im1 = (unsigned)(d - j) - 1u;   // i-1
        r2 = r1;
        if (im1 < 256u) r1 = rn;                 // active: 1 <= i <= 256

        if (lane == 31) bnd[d & 1][w] = make_float2(r1, r2);
        __syncthreads();
    }

    if (t == 255) atomicAdd(out, r1 * (LN2 / 64.0f));
}

extern "C" void kernel_launch(void* const* d_in, const int* in_sizes, int n_in,
                              void* d_out, int out_size) {
    const float* x = (const float*)d_in[0];
    const float* y = (const float*)d_in[1];
    float* out = (float*)d_out;
    prep_kernel<<<4096, 256>>>(x, y, out);
    cost_gemm_kernel<<<256, 256>>>();
    dp_kernel<<<64, 256>>>(out);
}

// round 10
// speedup vs baseline: 3.1437x; 1.3110x over previous
#include <cuda_runtime.h>
#include <cuda_bf16.h>
#include <cstdint>
#include <cstddef>

#define LOG2E 1.4426950408889634f
#define LN2   0.6931471805599453f

// ---- static scratch ----
// cost in diag layout [b][i+j][j], log2e-scaled, padded by 4 rows for branchless prefetch
__device__ float g_cost[64 * 512 * 256 + 1024];
__device__ float g_xn[64 * 256];                // log2e * |x_i|^2
__device__ float g_yn[64 * 256];
__device__ unsigned short g_xb[64 * 256 * 128]; // bf16 bits of x
__device__ unsigned short g_yb[64 * 256 * 128]; // bf16 bits of y

__device__ __forceinline__ float ex2f(float x) {
    float y; asm("ex2.approx.f32 %0, %1;" : "=f"(y) : "f"(x)); return y;
}
__device__ __forceinline__ float lg2f(float x) {
    float y; asm("lg2.approx.f32 %0, %1;" : "=f"(y) : "f"(x)); return y;
}
__device__ __forceinline__ uint32_t sptr(const void* p) {
    return (uint32_t)__cvta_generic_to_shared(p);
}
// stable soft-min of 3 in log2 domain
__device__ __forceinline__ float sm3(float a, float b, float c) {
    float mn = fminf(a, b), mx = fmaxf(a, b);
    float lo  = fminf(mn, c);
    float mid = fmaxf(mn, fminf(mx, c));
    float hi  = fmaxf(mx, c);
    return lo - lg2f(1.0f + ex2f(lo - mid) + ex2f(lo - hi));
}

// ================= K0: norms + bf16 convert (warp per row) =================
__global__ void __launch_bounds__(256) prep_kernel(const float* __restrict__ x,
                                                   const float* __restrict__ y,
                                                   float* __restrict__ out) {
    int gw = blockIdx.x * 8 + (threadIdx.x >> 5);
    int lane = threadIdx.x & 31;
    bool isx = gw < 16384;
    int rowg = isx ? gw : gw - 16384;  // b*256 + r
    const float* src = (isx ? x : y) + (size_t)rowg * 128 + lane * 4;
    float4 f = *(const float4*)src;
    float s = f.x * f.x;
    s = fmaf(f.y, f.y, s); s = fmaf(f.z, f.z, s); s = fmaf(f.w, f.w, s);
#pragma unroll
    for (int off = 16; off >= 1; off >>= 1) s += __shfl_xor_sync(0xffffffffu, s, off);
    if (lane == 0) (isx ? g_xn : g_yn)[rowg] = s * LOG2E;
    ushort4 s4;
    s4.x = __bfloat16_as_ushort(__float2bfloat16(f.x));
    s4.y = __bfloat16_as_ushort(__float2bfloat16(f.y));
    s4.z = __bfloat16_as_ushort(__float2bfloat16(f.z));
    s4.w = __bfloat16_as_ushort(__float2bfloat16(f.w));
    *(ushort4*)((isx ? g_xb : g_yb) + (size_t)rowg * 128 + lane * 4) = s4;
    if (blockIdx.x == 0 && threadIdx.x == 0) out[0] = 0.f;
}

// ================= K1: bf16 mma cost GEMM, diag-coalesced epilogue =================
// 256 blocks = 64 batches x (2x2 tiles of 128x128). 8 warps, warp tile 32(m) x 64(n).
__global__ void __launch_bounds__(256) cost_gemm_kernel() {
    __shared__ __align__(16) char smraw[33280];
    unsigned short* Xs = (unsigned short*)smraw;       // [128][64] bf16, swizzled
    unsigned short* Ys = Xs + 128 * 64;
    float* Cs = (float*)smraw;                          // [64][130]

    int bx = blockIdx.x;
    int b = bx >> 2, tm = (bx >> 1) & 1, tn = bx & 1;
    int t = threadIdx.x, lane = t & 31, w = t >> 5;
    int wr = w >> 1, wc = w & 1;

    const unsigned short* Xg = g_xb + ((size_t)(b * 256 + tm * 128)) * 128;
    const unsigned short* Yg = g_yb + ((size_t)(b * 256 + tn * 128)) * 128;

    float acc[2][8][4];
#pragma unroll
    for (int am = 0; am < 2; am++)
#pragma unroll
        for (int bn = 0; bn < 8; bn++)
#pragma unroll
            for (int k = 0; k < 4; k++) acc[am][bn][k] = 0.f;

    int arow0 = 32 * wr + (lane & 15);
    int ahalf = lane >> 4;
    int brow0 = 64 * wc + (lane & 7) + ((lane >> 4) << 3);
    int bhalf = (lane >> 3) & 1;

    for (int kc = 0; kc < 128; kc += 64) {
        __syncthreads();
#pragma unroll
        for (int p = 0; p < 4; p++) {
            int u = t + 256 * p;
            int row = u >> 3, c16 = u & 7;
            uint4 vx = *(const uint4*)(Xg + (size_t)row * 128 + kc + c16 * 8);
            uint4 vy = *(const uint4*)(Yg + (size_t)row * 128 + kc + c16 * 8);
            int soff = row * 128 + ((c16 ^ (row & 7)) << 4);
            *(uint4*)((char*)Xs + soff) = vx;
            *(uint4*)((char*)Ys + soff) = vy;
        }
        __syncthreads();
#pragma unroll
        for (int ks = 0; ks < 4; ks++) {
            uint32_t a[2][4], bf[8][2];
#pragma unroll
            for (int am = 0; am < 2; am++) {
                int row = arow0 + 16 * am;
                int kb16 = ks * 2 + ahalf;
                uint32_t ad = sptr((char*)Xs + row * 128 + ((kb16 ^ (row & 7)) << 4));
                asm volatile("ldmatrix.sync.aligned.m8n8.x4.shared.b16 {%0,%1,%2,%3},[%4];"
                    : "=r"(a[am][0]), "=r"(a[am][1]), "=r"(a[am][2]), "=r"(a[am][3]) : "r"(ad));
            }
#pragma unroll
            for (int bp = 0; bp < 4; bp++) {
                int row = brow0 + 16 * bp;
                int kb16 = ks * 2 + bhalf;
                uint32_t ad = sptr((char*)Ys + row * 128 + ((kb16 ^ (row & 7)) << 4));
                asm volatile("ldmatrix.sync.aligned.m8n8.x4.shared.b16 {%0,%1,%2,%3},[%4];"
                    : "=r"(bf[2 * bp][0]), "=r"(bf[2 * bp][1]),
                      "=r"(bf[2 * bp + 1][0]), "=r"(bf[2 * bp + 1][1]) : "r"(ad));
            }
#pragma unroll
            for (int am = 0; am < 2; am++)
#pragma unroll
                for (int bn = 0; bn < 8; bn++)
                    asm volatile("mma.sync.aligned.m16n8k16.row.col.f32.bf16.bf16.f32 "
                        "{%0,%1,%2,%3},{%4,%5,%6,%7},{%8,%9},{%0,%1,%2,%3};"
                        : "+f"(acc[am][bn][0]), "+f"(acc[am][bn][1]),
                          "+f"(acc[am][bn][2]), "+f"(acc[am][bn][3])
                        : "r"(a[am][0]), "r"(a[am][1]), "r"(a[am][2]), "r"(a[am][3]),
                          "r"(bf[bn][0]), "r"(bf[bn][1]));
        }
    }

    // epilogue: stage to smem in 2 row-halves, then coalesced diag-major stores
    __syncthreads();
    float* cb = g_cost + (size_t)b * 512 * 256;
    const float* xn = g_xn + b * 256;
    const float* yn = g_yn + b * 256;

#pragma unroll
    for (int h = 0; h < 2; h++) {
        if ((wr >> 1) == h) {
            int rbase = 32 * (wr & 1);
#pragma unroll
            for (int am = 0; am < 2; am++)
#pragma unroll
                for (int bn = 0; bn < 8; bn++) {
                    int rr = rbase + 16 * am + (lane >> 2);
                    int cc = 64 * wc + 8 * bn + 2 * (lane & 3);
                    *(float2*)&Cs[rr * 130 + cc] = make_float2(acc[am][bn][0], acc[am][bn][1]);
                    *(float2*)&Cs[(rr + 8) * 130 + cc] = make_float2(acc[am][bn][2], acc[am][bn][3]);
                }
        }
        __syncthreads();
        int tt = t & 127;
        for (int s2 = 0; s2 < 192; s2 += 2) {
            int s = s2 + (t >> 7);                 // local diag within half: 0..191
            int lj_lo = max(0, s - 63), lj_hi = min(127, s);
            int lj = lj_lo + tt;
            if (s < 191 && lj <= lj_hi) {
                int li = s - lj;
                int i = tm * 128 + 64 * h + li;
                int j = tn * 128 + lj;
                float v = xn[i] + yn[j] - (2.0f * LOG2E) * Cs[li * 130 + lj];
                cb[(size_t)(i + j) * 256 + j] = v;
            }
        }
        __syncthreads();
    }
}

// ================= K2: 2-diagonal-per-barrier wavefront soft-DTW =================
// 64 blocks (1/batch) x 128 threads (4 warps). Thread t owns columns jA=2t+1, jB=2t+2.
// Each iteration computes anti-diagonals d=2k+2 and d+1 with ONE barrier:
// cross-warp gap for diag d+1 closed by redundant computation of the boundary cell
// from 5 published values. Loop body is branchless (SEL only), cost prefetch depth 2.
__global__ void __launch_bounds__(128) dp_kernel(float* __restrict__ out) {
    __shared__ float4 bndP[2][5];   // [parity][slot] {r1A,r2A,r1B,r2B} of warp slot-1's lane31
    __shared__ float  bndC[2][5];   // cost element for the redundant boundary cell

    int t = threadIdx.x, lane = t & 31, w = t >> 5, b = blockIdx.x;
    const float INF = __int_as_float(0x7f800000);
    const float* cost = g_cost + (size_t)b * 512 * 256 + 2 * t;

    if (t < 10) {
        ((float4*)bndP)[t] = make_float4(INF, INF, INF, INF);
        ((float*)bndC)[t] = 0.0f;
    }
    __syncthreads();

    float r1A = INF, r2A = INF, r1B = INF, r2B = INF;
    float2 e0 = *(const float2*)(cost + 0 * 256);   // row 2k   (d-2)
    float2 o0 = *(const float2*)(cost + 1 * 256);   // row 2k+1 (d-1)
    float2 e1 = *(const float2*)(cost + 2 * 256);
    float2 o1 = *(const float2*)(cost + 3 * 256);

    int jA = 2 * t + 1;
    bool p0 = (t == 0);
    bool isL0 = (lane == 0);
    bool isL31 = (lane == 31);
    int jR = 64 * w;                 // boundary column left of this warp

    for (int k = 0; k < 256; ++k) {
        int d = 2 * k + 2;
        int par = k & 1;

        float sh1 = __shfl_up_sync(0xffffffffu, r1B, 1);
        float sh2 = __shfl_up_sync(0xffffffffu, r2B, 1);
        float4 P = bndP[par][w];     // uniform per warp (broadcast)
        float Pc = bndC[par][w];
        float lbA1 = isL0 ? P.z : sh1;     // R[d-1][jA-1]
        float lbA2 = isL0 ? P.w : sh2;     // R[d-2][jA-1]
        if (p0) { lbA1 = INF; lbA2 = (k == 0) ? 0.0f : INF; }

        // ---- diagonal d ----
        float rdA = e0.x + sm3(r1A, lbA1, lbA2);
        float rdB = e0.y + sm3(r1B, r1A, r2A);
        float rr  = Pc  + sm3(P.z,  P.x,  P.y);    // redundant boundary cell (col jR, diag d)

        unsigned iA = (unsigned)(d - jA);
        float r1A_mid = ((iA - 1u) < 256u) ? rdA : r1A;   // R[d][jA] effective
        float r1B_mid = ((iA - 2u) < 256u) ? rdB : r1B;   // R[d][jB] effective
        float rr_eff  = ((unsigned)(d - jR - 1) < 256u) ? rr : INF;  // R[d][jR] eff

        // ---- diagonal d+1 ----
        float shm = __shfl_up_sync(0xffffffffu, r1B_mid, 1);
        float lbA1p = isL0 ? rr_eff : shm;  // R[d][jA-1]
        if (p0) lbA1p = INF;
        float rdAp = o0.x + sm3(r1A_mid, lbA1p, lbA1);     // dl = R[d-1][jA-1]
        float rdBp = o0.y + sm3(r1B_mid, r1A_mid, r1A);    // dl = R[d-1][jA]

        r2A = r1A_mid;
        r1A = ((iA + 0u) < 256u) ? rdAp : r1A_mid;   // (d+1)-jA - 1 = iA
        r2B = r1B_mid;
        r1B = ((iA - 1u) < 256u) ? rdBp : r1B_mid;   // (d+1)-jB - 1 = iA-1

        // publish for next iteration's consumer (warp w+1)
        if (isL31) {
            bndP[par ^ 1][w + 1] = make_float4(r1A, r2A, r1B, r2B);
            bndC[par ^ 1][w + 1] = e1.y;   // cost row 2k+2, col jB-1
        }
        __syncthreads();

        // shift cost pipeline (pad rows make this branchless-safe)
        e0 = e1; o0 = o1;
        e1 = *(const float2*)(cost + (size_t)(2 * k + 4) * 256);
        o1 = *(const float2*)(cost + (size_t)(2 * k + 5) * 256);
    }

    // t=127 col jB=256: r1B = R[512][256]
    if (t == 127) atomicAdd(out, r1B * (LN2 / 64.0f));
}

extern "C" void kernel_launch(void* const* d_in, const int* in_sizes, int n_in,
                              void* d_out, int out_size) {
    const float* x = (const float*)d_in[0];
    const float* y = (const float*)d_in[1];
    float* out = (float*)d_out;
    prep_kernel<<<4096, 256>>>(x, y, out);
    cost_gemm_kernel<<<256, 256>>>();
    dp_kernel<<<64, 128>>>(out);
}